// round 8
// baseline (speedup 1.0000x reference)
#include <cuda_runtime.h>
#include <math.h>
#include <stdint.h>

#define B_ 32
#define T_ 512
#define V_ 8000
#define E_ 256
#define U_ 512
#define G4 (4*U_)     // 2048
#define BT (B_*T_)    // 16384
#define HS2 1036      // padded duplicated-h row stride (floats)

// ---------------- static device scratch ----------------
__device__ float g_x  [BT*E_];
__device__ float g_xw0[(size_t)BT*G4];
__device__ float g_xw1[(size_t)BT*G4];
__device__ float g_h1 [(size_t)BT*2*U_];
__device__ float g_h2 [(size_t)BT*2*U_];
__device__ float g_wr [2][U_*G4];
__device__ float g_hs [2][2][B_*U_];
__device__ unsigned g_gen[2];
__device__ unsigned g_cnt[2];

// ---------------- f32x2 helpers ----------------
typedef unsigned long long ull;
__device__ __forceinline__ ull ffma2(ull a, ull b, ull c) {
    ull d;
    asm("fma.rn.f32x2 %0, %1, %2, %3;" : "=l"(d) : "l"(a), "l"(b), "l"(c));
    return d;
}
__device__ __forceinline__ float2 unpack2(ull v) {
    float2 r;
    asm("mov.b64 {%0, %1}, %2;" : "=f"(r.x), "=f"(r.y) : "l"(v));
    return r;
}

// ---------------- embedding gather ----------------
__global__ void embed_k(const int* __restrict__ tok, const float* __restrict__ emb) {
    int i = blockIdx.x * blockDim.x + threadIdx.x;
    int row  = i >> 6;
    int col4 = i & 63;
    int t = tok[row];
    reinterpret_cast<float4*>(g_x)[i] =
        reinterpret_cast<const float4*>(emb + (size_t)t * E_)[col4];
}

// ---------------- Wr reorder: [k][g*U+u] -> [k][u*4+g] ----------------
__global__ void reorder_k(const float* __restrict__ rf, const float* __restrict__ rb) {
    int i = blockIdx.x * 256 + threadIdx.x;
    int k = i / G4;
    int c = i % G4;
    int u = c >> 2, g = c & 3;
    g_wr[0][i] = rf[(size_t)k * G4 + g * U_ + u];
    g_wr[1][i] = rb[(size_t)k * G4 + g * U_ + u];
}

// ---------------- f32x2 GEMM: C[M,N] = A[M,K] @ B[K,N] + bias ----------------
// 128x128x16 tiles, 256 threads, 8x8 per thread (as 8x4 f32x2 pairs).
// A duplicated in SMEM so the broadcast operand needs no packing.
__global__ __launch_bounds__(256)
void f32x2_gemm_k(const float* __restrict__ A, const float* __restrict__ B,
                  const float* __restrict__ bias, float* __restrict__ C,
                  int N, int K)
{
    __shared__ float As2[16][256];   // duplicated A: col 2i, 2i+1 = a_i
    __shared__ float Bs [16][128];

    int tid = threadIdx.x;
    int ty = tid >> 4, tx = tid & 15;
    int rowBase = blockIdx.y * 128, colBase = blockIdx.x * 128;
    int arow = tid >> 1, acol = (tid & 1) * 4;
    int brow = tid >> 5, bcol = (tid & 31) * 4;
    int gcol = colBase + bcol;

    ull acc[8][4];
#pragma unroll
    for (int i = 0; i < 8; i++)
#pragma unroll
        for (int j = 0; j < 4; j++) acc[i][j] = 0ULL;

    const int nc = K >> 4;
    const float* Ap = A + (size_t)(rowBase + arow) * K + acol;

    float4 avr0, avr1, bvr0, bvr1;
    auto ldg = [&](int chunk) {
        int k0 = chunk << 4;
        avr0 = *(const float4*)(Ap + k0);
        avr1 = *(const float4*)(Ap + k0 + 8);
        if (gcol < N) {
            bvr0 = *(const float4*)(B + (size_t)(k0 + brow) * N + gcol);
            bvr1 = *(const float4*)(B + (size_t)(k0 + brow + 8) * N + gcol);
        } else {
            bvr0 = make_float4(0.f,0.f,0.f,0.f);
            bvr1 = bvr0;
        }
    };
    auto sts = [&]() {
        float a0[8] = {avr0.x,avr0.y,avr0.z,avr0.w, avr1.x,avr1.y,avr1.z,avr1.w};
#pragma unroll
        for (int s = 0; s < 2; s++)
#pragma unroll
            for (int q = 0; q < 4; q++) {
                float v = a0[s*4+q];
                *(float2*)&As2[acol + q + s*8][2*arow] = make_float2(v, v);
            }
        *(float4*)&Bs[brow][bcol]     = bvr0;
        *(float4*)&Bs[brow + 8][bcol] = bvr1;
    };

    ldg(0); sts();
    __syncthreads();

    for (int i = 0; i < nc; i++) {
        if (i + 1 < nc) ldg(i + 1);
#pragma unroll
        for (int k = 0; k < 16; k++) {
            ulonglong2 a01 = *(const ulonglong2*)&As2[k][ty*8];
            ulonglong2 a23 = *(const ulonglong2*)&As2[k][ty*8 + 4];
            ulonglong2 a45 = *(const ulonglong2*)&As2[k][ty*8 + 128];
            ulonglong2 a67 = *(const ulonglong2*)&As2[k][ty*8 + 132];
            ulonglong2 b01 = *(const ulonglong2*)&Bs[k][tx*4];
            ulonglong2 b23 = *(const ulonglong2*)&Bs[k][tx*4 + 64];
            ull ap[8] = {a01.x, a01.y, a23.x, a23.y, a45.x, a45.y, a67.x, a67.y};
            ull bp[4] = {b01.x, b01.y, b23.x, b23.y};
#pragma unroll
            for (int ii = 0; ii < 8; ii++)
#pragma unroll
                for (int jp = 0; jp < 4; jp++)
                    acc[ii][jp] = ffma2(ap[ii], bp[jp], acc[ii][jp]);
        }
        __syncthreads();
        if (i + 1 < nc) {
            sts();
            __syncthreads();
        }
    }

    // ---- epilogue ----
    // acc[ii][jp]: rows ty*4 + {0..3, 64..67}; col pairs:
    //   jp=0 -> tx*4+0,1   jp=1 -> tx*4+2,3   jp=2 -> tx*4+64,65   jp=3 -> tx*4+66,67
#pragma unroll
    for (int ii = 0; ii < 8; ii++) {
        int r = rowBase + ty*4 + ((ii < 4) ? ii : (60 + ii));
#pragma unroll
        for (int jp = 0; jp < 4; jp++) {
            int col = colBase + tx*4 + ((jp < 2) ? jp*2 : (60 + jp*2));
            if (col < N) {
                float2 v = unpack2(acc[ii][jp]);
                v.x += bias[col];
                v.y += bias[col + 1];
                *(float2*)&C[(size_t)r * N + col] = v;
            }
        }
    }
}

// ---------------- software grid barrier ----------------
__device__ __forceinline__ void grid_barrier(int dir) {
    __syncthreads();
    if (threadIdx.x == 0) {
        __threadfence();
        volatile unsigned* gen = &g_gen[dir];
        unsigned old = *gen;
        unsigned a = atomicAdd(&g_cnt[dir], 1u);
        if (a == 63u) {
            g_cnt[dir] = 0u;
            __threadfence();
            *gen = old + 1u;
        } else {
            while (*gen == old) { }
        }
        __threadfence();
    }
    __syncthreads();
}

// ---------------- persistent bidirectional LSTM layer (f32x2) ----------------
__global__ __launch_bounds__(128)
void lstm_layer_k(const float* __restrict__ xwf, const float* __restrict__ xwb,
                  const int* __restrict__ tok, float* __restrict__ y)
{
    extern __shared__ float sm[];
    float* sw   = sm;                // [512][32] weight slice (64 KB)
    float* shh2 = sm + 512*32;       // [32][HS2] duplicated h (~130 KB)

    int dir = blockIdx.x >> 6;
    int ub  = blockIdx.x & 63;
    int u0  = ub * 8;
    int tid = threadIdx.x;
    int uloc = tid & 7;
    int bp   = tid >> 3;
    int b0 = bp * 2, b1 = b0 + 1;
    int u = u0 + uloc;

    const float* xw = dir ? xwb : xwf;
    const float* wr = g_wr[dir];

    for (int i = tid; i < 512*8; i += 128) {
        int k  = i >> 3;
        int c4 = i & 7;
        ((float4*)sw)[i] = *(const float4*)&wr[(size_t)k * G4 + u0*4 + c4*4];
    }
    for (int i = tid; i < 8*32; i += 128) {
        int bb = i >> 3;
        g_hs[dir][0][bb * U_ + u0 + (i & 7)] = 0.f;
    }
    float c0 = 0.f, c1 = 0.f, hp0 = 0.f, hp1 = 0.f;
    __threadfence();
    grid_barrier(dir);

    const ulonglong2* pw = (const ulonglong2*)sw;

    for (int s = 0; s < T_; s++) {
        int t = dir ? (T_ - 1 - s) : s;
        const float* hread  = g_hs[dir][s & 1];
        float*       hwrite = g_hs[dir][(s & 1) ^ 1];

        // Stage h duplicated: shh2[b][2k] = shh2[b][2k+1] = h[b][k]
        for (int i = tid; i < 32*128; i += 128) {
            int bb = i >> 7;
            int kq = i & 127;
            float4 v = *(const float4*)&hread[bb * U_ + kq*4];
            *(float4*)&shh2[bb*HS2 + kq*8]     = make_float4(v.x, v.x, v.y, v.y);
            *(float4*)&shh2[bb*HS2 + kq*8 + 4] = make_float4(v.z, v.z, v.w, v.w);
        }
        __syncthreads();

        ull A0 = 0ULL, B0 = 0ULL, A1 = 0ULL, B1 = 0ULL;  // (i,f),(g,o) per batch
        const ulonglong2* ph0 = (const ulonglong2*)&shh2[b0 * HS2];
        const ulonglong2* ph1 = (const ulonglong2*)&shh2[b1 * HS2];

#pragma unroll 8
        for (int m = 0; m < 256; m++) {          // 2 k per iter
            ulonglong2 h0 = ph0[m];
            ulonglong2 h1 = ph1[m];
            ulonglong2 w0 = pw[(2*m)   * 8 + uloc];
            ulonglong2 w1 = pw[(2*m+1) * 8 + uloc];
            A0 = ffma2(h0.x, w0.x, A0);  B0 = ffma2(h0.x, w0.y, B0);
            A1 = ffma2(h1.x, w0.x, A1);  B1 = ffma2(h1.x, w0.y, B1);
            A0 = ffma2(h0.y, w1.x, A0);  B0 = ffma2(h0.y, w1.y, B0);
            A1 = ffma2(h1.y, w1.x, A1);  B1 = ffma2(h1.y, w1.y, B1);
        }

        {
            float2 if0 = unpack2(A0), go0 = unpack2(B0);
            size_t base = ((size_t)b0 * T_ + t) * G4;
            float zi = if0.x + xw[base + 0*U_ + u];
            float zf = if0.y + xw[base + 1*U_ + u];
            float zg = go0.x + xw[base + 2*U_ + u];
            float zo = go0.y + xw[base + 3*U_ + u];
            float ig = 1.f / (1.f + expf(-zi));
            float fg = 1.f / (1.f + expf(-zf));
            float gg = tanhf(zg);
            float og = 1.f / (1.f + expf(-zo));
            float cn = fg * c0 + ig * gg;
            float hn = og * tanhf(cn);
            if (tok[b0 * T_ + t] != 0) { c0 = cn; hp0 = hn; }
            hwrite[b0 * U_ + u] = hp0;
            y[((size_t)b0 * T_ + t) * (2*U_) + dir * U_ + u] = hp0;
        }
        {
            float2 if1 = unpack2(A1), go1 = unpack2(B1);
            size_t base = ((size_t)b1 * T_ + t) * G4;
            float zi = if1.x + xw[base + 0*U_ + u];
            float zf = if1.y + xw[base + 1*U_ + u];
            float zg = go1.x + xw[base + 2*U_ + u];
            float zo = go1.y + xw[base + 3*U_ + u];
            float ig = 1.f / (1.f + expf(-zi));
            float fg = 1.f / (1.f + expf(-zf));
            float gg = tanhf(zg);
            float og = 1.f / (1.f + expf(-zo));
            float cn = fg * c1 + ig * gg;
            float hn = og * tanhf(cn);
            if (tok[b1 * T_ + t] != 0) { c1 = cn; hp1 = hn; }
            hwrite[b1 * U_ + u] = hp1;
            y[((size_t)b1 * T_ + t) * (2*U_) + dir * U_ + u] = hp1;
        }

        __threadfence();
        grid_barrier(dir);
    }
}

// ---------------- host ----------------
extern "C" void kernel_launch(void* const* d_in, const int* in_sizes, int n_in,
                              void* d_out, int out_size)
{
    const int*   tokens = (const int*)  d_in[0];
    const float* emb    = (const float*)d_in[1];
    const float* k1f    = (const float*)d_in[2];
    const float* r1f    = (const float*)d_in[3];
    const float* b1f    = (const float*)d_in[4];
    const float* k1b    = (const float*)d_in[5];
    const float* r1b    = (const float*)d_in[6];
    const float* b1b    = (const float*)d_in[7];
    const float* k2f    = (const float*)d_in[8];
    const float* r2f    = (const float*)d_in[9];
    const float* b2f    = (const float*)d_in[10];
    const float* k2b    = (const float*)d_in[11];
    const float* r2b    = (const float*)d_in[12];
    const float* b2b    = (const float*)d_in[13];
    const float* wd     = (const float*)d_in[14];
    const float* bd     = (const float*)d_in[15];
    float* out = (float*)d_out;

    static float *px = nullptr, *pxw0, *pxw1, *ph1, *ph2;
    if (!px) {
        cudaGetSymbolAddress((void**)&px,   g_x);
        cudaGetSymbolAddress((void**)&pxw0, g_xw0);
        cudaGetSymbolAddress((void**)&pxw1, g_xw1);
        cudaGetSymbolAddress((void**)&ph1,  g_h1);
        cudaGetSymbolAddress((void**)&ph2,  g_h2);
        cudaFuncSetAttribute(lstm_layer_k,
                             cudaFuncAttributeMaxDynamicSharedMemorySize,
                             (512*32 + 32*HS2) * sizeof(float));
    }
    const int lstm_smem = (512*32 + 32*HS2) * sizeof(float);

    embed_k<<<(BT*E_/4)/256, 256>>>(tokens, emb);

    // ---- layer 1 (K=256, N=2048) ----
    reorder_k<<<(U_*G4)/256, 256>>>(r1f, r1b);
    f32x2_gemm_k<<<dim3(G4/128, BT/128), 256>>>(px, k1f, b1f, pxw0, G4, E_);
    f32x2_gemm_k<<<dim3(G4/128, BT/128), 256>>>(px, k1b, b1b, pxw1, G4, E_);
    lstm_layer_k<<<128, 128, lstm_smem>>>(pxw0, pxw1, tokens, ph1);

    // ---- layer 2 (K=1024, N=2048) ----
    reorder_k<<<(U_*G4)/256, 256>>>(r2f, r2b);
    f32x2_gemm_k<<<dim3(G4/128, BT/128), 256>>>(ph1, k2f, b2f, pxw0, G4, 2*U_);
    f32x2_gemm_k<<<dim3(G4/128, BT/128), 256>>>(ph1, k2b, b2b, pxw1, G4, 2*U_);
    lstm_layer_k<<<128, 128, lstm_smem>>>(pxw0, pxw1, tokens, ph2);

    // ---- output projection (K=1024, N=8000) ----
    f32x2_gemm_k<<<dim3((V_ + 127)/128, BT/128), 256>>>(ph2, wd, bd, out, V_, 2*U_);
}

// round 9
// speedup vs baseline: 1.6326x; 1.6326x over previous
#include <cuda_runtime.h>
#include <math.h>
#include <stdint.h>

#define B_ 32
#define T_ 512
#define V_ 8000
#define E_ 256
#define U_ 512
#define G4 (4*U_)     // 2048
#define BT (B_*T_)    // 16384
#define HSTRIDE 516
#define VPAD 8064     // V padded to multiple of 128

#define ASTG 2560     // 128 rows * 20 floats per A stage
#define BSTG 2048     // 2 k8 * 8 pairs * 32 lanes * 4 floats per B stage

// ---------------- static device scratch ----------------
__device__ float g_x  [BT*E_];
__device__ float g_xw0[(size_t)BT*G4];
__device__ float g_xw1[(size_t)BT*G4];
__device__ float g_h1 [(size_t)BT*2*U_];
__device__ float g_h2 [(size_t)BT*2*U_];
__device__ float g_wr [2][U_*G4];
__device__ float g_hs [2][2][B_*U_];
__device__ float g_wdT[(size_t)VPAD*2*U_];    // packed dense weights
__device__ float g_kT [2][(size_t)G4*2*U_];   // packed kernel weights (per dir)
__device__ unsigned g_gen[2];
__device__ unsigned g_cnt[2];

// ---------------- helpers ----------------
__device__ __forceinline__ uint32_t smem_u32(const void* p) {
    uint32_t a;
    asm("{ .reg .u64 t; cvta.to.shared.u64 t, %1; cvt.u32.u64 %0, t; }" : "=r"(a) : "l"(p));
    return a;
}
__device__ __forceinline__ float rna_tf32f(float x) {
    uint32_t r; asm("cvt.rna.tf32.f32 %0, %1;" : "=r"(r) : "f"(x));
    return __uint_as_float(r);
}
__device__ __forceinline__ void cp16(uint32_t dst, const void* src) {
    asm volatile("cp.async.ca.shared.global [%0], [%1], 16;" :: "r"(dst), "l"(src));
}
__device__ __forceinline__ void cp_commit() {
    asm volatile("cp.async.commit_group;" ::: "memory");
}
template <int N>
__device__ __forceinline__ void cp_wait() {
    asm volatile("cp.async.wait_group %0;" :: "n"(N) : "memory");
}
__device__ __forceinline__ void mma_tf32(float c[4], const uint32_t a[4], uint32_t b0, uint32_t b1) {
    asm volatile(
        "mma.sync.aligned.m16n8k8.row.col.f32.tf32.tf32.f32 "
        "{%0,%1,%2,%3}, {%4,%5,%6,%7}, {%8,%9}, {%0,%1,%2,%3};"
        : "+f"(c[0]), "+f"(c[1]), "+f"(c[2]), "+f"(c[3])
        : "r"(a[0]), "r"(a[1]), "r"(a[2]), "r"(a[3]), "r"(b0), "r"(b1));
}

// ---------------- embedding gather (tf32-round for GEMM A) ----------------
__global__ void embed_k(const int* __restrict__ tok, const float* __restrict__ emb) {
    int i = blockIdx.x * blockDim.x + threadIdx.x;
    int row  = i >> 6;
    int col4 = i & 63;
    int t = tok[row];
    float4 v = reinterpret_cast<const float4*>(emb + (size_t)t * E_)[col4];
    v.x = rna_tf32f(v.x); v.y = rna_tf32f(v.y);
    v.z = rna_tf32f(v.z); v.w = rna_tf32f(v.w);
    reinterpret_cast<float4*>(g_x)[i] = v;
}

// ---------------- Wr reorder: [k][g*U+u] -> [k][u*4+g] ----------------
__global__ void reorder_k(const float* __restrict__ rf, const float* __restrict__ rb) {
    int i = blockIdx.x * 256 + threadIdx.x;
    int k = i / G4;
    int c = i % G4;
    int u = c >> 2, g = c & 3;
    g_wr[0][i] = rf[(size_t)k * G4 + g * U_ + u];
    g_wr[1][i] = rb[(size_t)k * G4 + g * U_ + u];
}

// ---------------- pack B[K][N] -> fragment-ordered [bc][K/8][pair][lane][4] ----------------
__global__ void pack_b_k(const float* __restrict__ in, float* __restrict__ out,
                         int K, int N) {
    size_t o = (size_t)blockIdx.x * 256 + threadIdx.x;
    int per_bc = K * 128;
    int bc  = (int)(o / per_bc);
    int rem = (int)(o % per_bc);
    int kt   = rem >> 10;
    int r2   = rem & 1023;
    int pair = r2 >> 7;
    int lane = (r2 >> 2) & 31;
    int r    = r2 & 3;
    int ntile = 2*pair + (r >> 1);
    int k = kt*8 + (lane & 3) + (r & 1)*4;
    int n = bc*128 + ntile*8 + (lane >> 2);
    float v = (n < N) ? in[(size_t)k * N + n] : 0.f;
    out[o] = rna_tf32f(v);
}

// ---------------- tf32 mma GEMM: C = A[M,K] @ B + bias, B fragment-packed ----------------
// grid (Npad/128, M/128), 256 threads (8 warps: wm 0-3 x wn 0-1), warp tile 32x64.
// 4-stage cp.async pipeline, BK=16.
__global__ __launch_bounds__(256)
void tf32_gemm_k(const float* __restrict__ A, const float* __restrict__ Bp,
                 const float* __restrict__ bias, float* __restrict__ C,
                 int N, int K)
{
    extern __shared__ float sm[];
    float* As = sm;                 // 4 * ASTG
    float* Bs = sm + 4*ASTG;        // 4 * BSTG

    int tid = threadIdx.x;
    int wid = tid >> 5, lane = tid & 31;
    int wm = wid >> 1, wn = wid & 1;
    int gid = lane >> 2, tg = lane & 3;
    int rowBase = blockIdx.y * 128;
    int bc = blockIdx.x;
    int colBase = bc * 128;
    const float* Bsrc = Bp + (size_t)bc * K * 128;

    float c[2][8][4];
#pragma unroll
    for (int i = 0; i < 2; i++)
#pragma unroll
        for (int j = 0; j < 8; j++)
#pragma unroll
            for (int q = 0; q < 4; q++) c[i][j][q] = 0.f;

    const int nc = K >> 4;

    auto stage = [&](int chunk, int slot) {
#pragma unroll
        for (int it = 0; it < 2; it++) {
            int idx = it * 256 + tid;
            int row = idx >> 2, c4 = idx & 3;
            cp16(smem_u32(&As[slot*ASTG + row*20 + c4*4]),
                 A + (size_t)(rowBase + row) * K + chunk*16 + c4*4);
            cp16(smem_u32(&Bs[slot*BSTG + idx*4]),
                 Bsrc + (size_t)chunk * BSTG + idx*4);
        }
    };

    stage(0, 0); cp_commit();
    stage(1, 1); cp_commit();

    for (int i = 0; i < nc; i++) {
        if (i + 2 < nc) stage(i + 2, (i + 2) & 3);
        cp_commit();
        cp_wait<2>();
        __syncthreads();

        int slot = i & 3;
        const uint32_t* Au = (const uint32_t*)&As[slot*ASTG];
        const float*    Bu = &Bs[slot*BSTG];
#pragma unroll
        for (int k8 = 0; k8 < 2; k8++) {
            uint32_t af[2][4];
#pragma unroll
            for (int mt = 0; mt < 2; mt++) {
                int base = (wm*32 + mt*16 + gid)*20 + k8*8 + tg;
                af[mt][0] = Au[base];
                af[mt][1] = Au[base + 160];
                af[mt][2] = Au[base + 4];
                af[mt][3] = Au[base + 164];
            }
#pragma unroll
            for (int p = 0; p < 4; p++) {
                float4 bv = *(const float4*)&Bu[k8*1024 + ((wn*4 + p)*32 + lane)*4];
                uint32_t b0 = __float_as_uint(bv.x), b1 = __float_as_uint(bv.y);
                uint32_t b2 = __float_as_uint(bv.z), b3 = __float_as_uint(bv.w);
                mma_tf32(c[0][2*p],   af[0], b0, b1);
                mma_tf32(c[0][2*p+1], af[0], b2, b3);
                mma_tf32(c[1][2*p],   af[1], b0, b1);
                mma_tf32(c[1][2*p+1], af[1], b2, b3);
            }
        }
    }

    // ---- epilogue: direct stores (+bias) ----
#pragma unroll
    for (int mt = 0; mt < 2; mt++) {
        int r0 = rowBase + wm*32 + mt*16 + gid;
#pragma unroll
        for (int nb = 0; nb < 8; nb++) {
            int col = colBase + wn*64 + nb*8 + tg*2;
            if (col < N) {
                float b0 = bias[col], b1 = bias[col + 1];
                *(float2*)&C[(size_t)r0 * N + col] =
                    make_float2(c[mt][nb][0] + b0, c[mt][nb][1] + b1);
                *(float2*)&C[(size_t)(r0 + 8) * N + col] =
                    make_float2(c[mt][nb][2] + b0, c[mt][nb][3] + b1);
            }
        }
    }
}

// ---------------- software grid barrier ----------------
__device__ __forceinline__ void grid_barrier(int dir) {
    __syncthreads();
    if (threadIdx.x == 0) {
        __threadfence();
        volatile unsigned* gen = &g_gen[dir];
        unsigned old = *gen;
        unsigned a = atomicAdd(&g_cnt[dir], 1u);
        if (a == 63u) {
            g_cnt[dir] = 0u;
            __threadfence();
            *gen = old + 1u;
        } else {
            while (*gen == old) { }
        }
        __threadfence();
    }
    __syncthreads();
}

// ---------------- persistent bidirectional LSTM layer (scalar fp32) ----------------
__global__ __launch_bounds__(128)
void lstm_layer_k(const float* __restrict__ xwf, const float* __restrict__ xwb,
                  const int* __restrict__ tok, float* __restrict__ y)
{
    extern __shared__ float sm[];
    float* sw  = sm;
    float* shh = sm + 512*32;

    int dir = blockIdx.x >> 6;
    int ub  = blockIdx.x & 63;
    int u0  = ub * 8;
    int tid = threadIdx.x;
    int uloc = tid & 7;
    int bp   = tid >> 3;
    int b0 = bp * 2, b1 = b0 + 1;
    int u = u0 + uloc;

    const float* xw = dir ? xwb : xwf;
    const float* wr = g_wr[dir];

    for (int i = tid; i < 512*8; i += 128) {
        int k  = i >> 3;
        int c4 = i & 7;
        ((float4*)sw)[i] = *(const float4*)&wr[(size_t)k * G4 + u0*4 + c4*4];
    }
    for (int i = tid; i < 8*32; i += 128) {
        int bb = i >> 3;
        g_hs[dir][0][bb * U_ + u0 + (i & 7)] = 0.f;
    }
    float c0 = 0.f, c1 = 0.f, hp0 = 0.f, hp1 = 0.f;
    __threadfence();
    grid_barrier(dir);

    for (int s = 0; s < T_; s++) {
        int t = dir ? (T_ - 1 - s) : s;
        const float* hread  = g_hs[dir][s & 1];
        float*       hwrite = g_hs[dir][(s & 1) ^ 1];

        for (int i = tid; i < 32*128; i += 128) {
            int bb = i >> 7;
            int kq = i & 127;
            *(float4*)&shh[bb * HSTRIDE + kq*4] =
                *(const float4*)&hread[bb * U_ + kq*4];
        }
        __syncthreads();

        float acc0[4] = {0.f,0.f,0.f,0.f};
        float acc1[4] = {0.f,0.f,0.f,0.f};
        const float* hr0 = &shh[b0 * HSTRIDE];
        const float* hr1 = &shh[b1 * HSTRIDE];

#pragma unroll 4
        for (int k = 0; k < U_; k += 4) {
            float4 hv0 = *(const float4*)&hr0[k];
            float4 hv1 = *(const float4*)&hr1[k];
            float h0a[4] = {hv0.x, hv0.y, hv0.z, hv0.w};
            float h1a[4] = {hv1.x, hv1.y, hv1.z, hv1.w};
#pragma unroll
            for (int j = 0; j < 4; j++) {
                float4 w = *(const float4*)&sw[(k + j)*32 + uloc*4];
                acc0[0] = fmaf(h0a[j], w.x, acc0[0]);
                acc0[1] = fmaf(h0a[j], w.y, acc0[1]);
                acc0[2] = fmaf(h0a[j], w.z, acc0[2]);
                acc0[3] = fmaf(h0a[j], w.w, acc0[3]);
                acc1[0] = fmaf(h1a[j], w.x, acc1[0]);
                acc1[1] = fmaf(h1a[j], w.y, acc1[1]);
                acc1[2] = fmaf(h1a[j], w.z, acc1[2]);
                acc1[3] = fmaf(h1a[j], w.w, acc1[3]);
            }
        }

        {
            size_t base = ((size_t)b0 * T_ + t) * G4;
            float zi = acc0[0] + xw[base + 0*U_ + u];
            float zf = acc0[1] + xw[base + 1*U_ + u];
            float zg = acc0[2] + xw[base + 2*U_ + u];
            float zo = acc0[3] + xw[base + 3*U_ + u];
            float ig = 1.f / (1.f + expf(-zi));
            float fg = 1.f / (1.f + expf(-zf));
            float gg = tanhf(zg);
            float og = 1.f / (1.f + expf(-zo));
            float cn = fg * c0 + ig * gg;
            float hn = og * tanhf(cn);
            if (tok[b0 * T_ + t] != 0) { c0 = cn; hp0 = hn; }
            hwrite[b0 * U_ + u] = hp0;
            y[((size_t)b0 * T_ + t) * (2*U_) + dir * U_ + u] = rna_tf32f(hp0);
        }
        {
            size_t base = ((size_t)b1 * T_ + t) * G4;
            float zi = acc1[0] + xw[base + 0*U_ + u];
            float zf = acc1[1] + xw[base + 1*U_ + u];
            float zg = acc1[2] + xw[base + 2*U_ + u];
            float zo = acc1[3] + xw[base + 3*U_ + u];
            float ig = 1.f / (1.f + expf(-zi));
            float fg = 1.f / (1.f + expf(-zf));
            float gg = tanhf(zg);
            float og = 1.f / (1.f + expf(-zo));
            float cn = fg * c1 + ig * gg;
            float hn = og * tanhf(cn);
            if (tok[b1 * T_ + t] != 0) { c1 = cn; hp1 = hn; }
            hwrite[b1 * U_ + u] = hp1;
            y[((size_t)b1 * T_ + t) * (2*U_) + dir * U_ + u] = rna_tf32f(hp1);
        }

        __threadfence();
        grid_barrier(dir);
    }
}

// ---------------- host ----------------
extern "C" void kernel_launch(void* const* d_in, const int* in_sizes, int n_in,
                              void* d_out, int out_size)
{
    const int*   tokens = (const int*)  d_in[0];
    const float* emb    = (const float*)d_in[1];
    const float* k1f    = (const float*)d_in[2];
    const float* r1f    = (const float*)d_in[3];
    const float* b1f    = (const float*)d_in[4];
    const float* k1b    = (const float*)d_in[5];
    const float* r1b    = (const float*)d_in[6];
    const float* b1b    = (const float*)d_in[7];
    const float* k2f    = (const float*)d_in[8];
    const float* r2f    = (const float*)d_in[9];
    const float* b2f    = (const float*)d_in[10];
    const float* k2b    = (const float*)d_in[11];
    const float* r2b    = (const float*)d_in[12];
    const float* b2b    = (const float*)d_in[13];
    const float* wd     = (const float*)d_in[14];
    const float* bd     = (const float*)d_in[15];
    float* out = (float*)d_out;

    static float *px = nullptr, *pxw0, *pxw1, *ph1, *ph2, *pwdT, *pkT0, *pkT1;
    if (!px) {
        cudaGetSymbolAddress((void**)&px,   g_x);
        cudaGetSymbolAddress((void**)&pxw0, g_xw0);
        cudaGetSymbolAddress((void**)&pxw1, g_xw1);
        cudaGetSymbolAddress((void**)&ph1,  g_h1);
        cudaGetSymbolAddress((void**)&ph2,  g_h2);
        cudaGetSymbolAddress((void**)&pwdT, g_wdT);
        cudaGetSymbolAddress((void**)&pkT0, g_kT);
        pkT1 = pkT0 + (size_t)G4 * 2 * U_;
        cudaFuncSetAttribute(lstm_layer_k,
                             cudaFuncAttributeMaxDynamicSharedMemorySize,
                             (512*32 + 32*HSTRIDE) * sizeof(float));
        cudaFuncSetAttribute(tf32_gemm_k,
                             cudaFuncAttributeMaxDynamicSharedMemorySize,
                             (4*ASTG + 4*BSTG) * sizeof(float));
    }
    const int lstm_smem = (512*32 + 32*HSTRIDE) * sizeof(float);
    const int gemm_smem = (4*ASTG + 4*BSTG) * sizeof(float);

    embed_k<<<(BT*E_/4)/256, 256>>>(tokens, emb);

    // ---- layer 1 (K=256, N=2048) ----
    reorder_k<<<(U_*G4)/256, 256>>>(r1f, r1b);
    pack_b_k<<<(G4*E_)/256, 256>>>(k1f, pkT0, E_, G4);
    pack_b_k<<<(G4*E_)/256, 256>>>(k1b, pkT1, E_, G4);
    tf32_gemm_k<<<dim3(G4/128, BT/128), 256, gemm_smem>>>(px, pkT0, b1f, pxw0, G4, E_);
    tf32_gemm_k<<<dim3(G4/128, BT/128), 256, gemm_smem>>>(px, pkT1, b1b, pxw1, G4, E_);
    lstm_layer_k<<<128, 128, lstm_smem>>>(pxw0, pxw1, tokens, ph1);

    // ---- layer 2 (K=1024, N=2048) ----
    reorder_k<<<(U_*G4)/256, 256>>>(r2f, r2b);
    pack_b_k<<<(G4*2*U_)/256, 256>>>(k2f, pkT0, 2*U_, G4);
    pack_b_k<<<(G4*2*U_)/256, 256>>>(k2b, pkT1, 2*U_, G4);
    tf32_gemm_k<<<dim3(G4/128, BT/128), 256, gemm_smem>>>(ph1, pkT0, b2f, pxw0, G4, 2*U_);
    tf32_gemm_k<<<dim3(G4/128, BT/128), 256, gemm_smem>>>(ph1, pkT1, b2b, pxw1, G4, 2*U_);
    lstm_layer_k<<<128, 128, lstm_smem>>>(pxw0, pxw1, tokens, ph2);

    // ---- output projection (K=1024, N=8000 padded 8064) ----
    pack_b_k<<<((size_t)VPAD*2*U_)/256, 256>>>(wd, pwdT, 2*U_, V_);
    tf32_gemm_k<<<dim3(VPAD/128, BT/128), 256, gemm_smem>>>(ph2, pwdT, bd, out, V_, 2*U_);
}

// round 10
// speedup vs baseline: 1.9672x; 1.2049x over previous
#include <cuda_runtime.h>
#include <cuda_fp16.h>
#include <math.h>
#include <stdint.h>

#define B_ 32
#define T_ 512
#define V_ 8000
#define E_ 256
#define U_ 512
#define G4 (4*U_)     // 2048
#define BT (B_*T_)    // 16384
#define HSTRIDE 516
#define VPAD 8064     // V padded to multiple of 128

#define ASTG 5120     // halves per A stage: 128 rows * 40
#define BSTG 2048     // b32 per B stage: 2 kt * 8 pg * 128

// ---------------- static device scratch ----------------
__device__ __half g_xh [BT*E_];              // embedded input (fp16)
__device__ float  g_xw0[(size_t)BT*G4];
__device__ float  g_xw1[(size_t)BT*G4];
__device__ __half g_h1h[(size_t)BT*2*U_];    // layer1 output (fp16)
__device__ __half g_h2h[(size_t)BT*2*U_];    // layer2 output (fp16)
__device__ float  g_wr [2][U_*G4];
__device__ float  g_hs [2][2][B_*U_];
__device__ __half2 g_wdP[(size_t)VPAD*2*U_/2];   // packed dense weights
__device__ __half2 g_kP [2][(size_t)G4*2*U_/2];  // packed kernel weights
__device__ unsigned g_gen[2];
__device__ unsigned g_cnt[2];

// ---------------- helpers ----------------
__device__ __forceinline__ uint32_t smem_u32(const void* p) {
    uint32_t a;
    asm("{ .reg .u64 t; cvta.to.shared.u64 t, %1; cvt.u32.u64 %0, t; }" : "=r"(a) : "l"(p));
    return a;
}
__device__ __forceinline__ void cp16(uint32_t dst, const void* src) {
    asm volatile("cp.async.ca.shared.global [%0], [%1], 16;" :: "r"(dst), "l"(src));
}
__device__ __forceinline__ void cp_commit() {
    asm volatile("cp.async.commit_group;" ::: "memory");
}
template <int N>
__device__ __forceinline__ void cp_wait() {
    asm volatile("cp.async.wait_group %0;" :: "n"(N) : "memory");
}
__device__ __forceinline__ void mma_f16(float c[4], const uint32_t a[4], uint32_t b0, uint32_t b1) {
    asm volatile(
        "mma.sync.aligned.m16n8k16.row.col.f32.f16.f16.f32 "
        "{%0,%1,%2,%3}, {%4,%5,%6,%7}, {%8,%9}, {%0,%1,%2,%3};"
        : "+f"(c[0]), "+f"(c[1]), "+f"(c[2]), "+f"(c[3])
        : "r"(a[0]), "r"(a[1]), "r"(a[2]), "r"(a[3]), "r"(b0), "r"(b1));
}

// ---------------- embedding gather -> fp16 ----------------
__global__ void embed_k(const int* __restrict__ tok, const float* __restrict__ emb) {
    int i = blockIdx.x * 256 + threadIdx.x;    // over BT*E/8
    int row = i >> 5;                           // 32 8-half chunks per row
    int c8  = i & 31;
    int t = tok[row];
    const float4* s = (const float4*)(emb + (size_t)t * E_ + c8 * 8);
    float4 v0 = s[0], v1 = s[1];
    __half2 h[4];
    h[0] = __floats2half2_rn(v0.x, v0.y);
    h[1] = __floats2half2_rn(v0.z, v0.w);
    h[2] = __floats2half2_rn(v1.x, v1.y);
    h[3] = __floats2half2_rn(v1.z, v1.w);
    *(uint4*)&g_xh[(size_t)row * E_ + c8 * 8] = *(uint4*)h;
}

// ---------------- Wr reorder: [k][g*U+u] -> [k][u*4+g] (fp32, for LSTM) ----------------
__global__ void reorder_k(const float* __restrict__ rf, const float* __restrict__ rb) {
    int i = blockIdx.x * 256 + threadIdx.x;
    int k = i / G4;
    int c = i % G4;
    int u = c >> 2, g = c & 3;
    g_wr[0][i] = rf[(size_t)k * G4 + g * U_ + u];
    g_wr[1][i] = rb[(size_t)k * G4 + g * U_ + u];
}

// ---------------- pack B[K][N] -> fp16 fragment order ----------------
// out b32 index: ((bc*(K/16)+kt)*8 + pg)*128 + lane*4 + r
__global__ void pack_b_k(const float* __restrict__ in, __half2* __restrict__ out,
                         int K, int N) {
    size_t o = (size_t)blockIdx.x * 256 + threadIdx.x;
    int per_bc = K * 64;
    int bc  = (int)(o / per_bc);
    int rem = (int)(o % per_bc);
    int kt = rem >> 10;
    int r2 = rem & 1023;
    int pg = r2 >> 7;
    int lr = r2 & 127;
    int lane = lr >> 2, r = lr & 3;
    int nt = 2*pg + (r >> 1);
    int breg = r & 1;
    int g = lane >> 2, t4 = lane & 3;
    int k = kt*16 + breg*8 + 2*t4;
    int n = bc*128 + nt*8 + g;
    float v0 = (n < N) ? in[(size_t)k * N + n] : 0.f;
    float v1 = (n < N) ? in[(size_t)(k+1) * N + n] : 0.f;
    out[o] = __floats2half2_rn(v0, v1);
}

// ---------------- fp16 mma GEMM: C = A[M,K](fp16) @ B(packed fp16) + bias ----------------
// grid (Npad/128, M/128), 256 threads (8 warps: 4m x 2n), warp tile 32x64, BK=32.
__global__ __launch_bounds__(256)
void f16_gemm_k(const __half* __restrict__ Ah, const __half2* __restrict__ Bp,
                const float* __restrict__ bias, float* __restrict__ C,
                int N, int K)
{
    extern __shared__ __half sm[];
    __half* As = sm;                                 // 4 * ASTG halves
    uint32_t* Bs = (uint32_t*)(sm + 4*ASTG);         // 4 * BSTG b32

    int tid = threadIdx.x;
    int wid = tid >> 5, lane = tid & 31;
    int wm = wid >> 1, wn = wid & 1;
    int gid = lane >> 2, tg = lane & 3;
    int rowBase = blockIdx.y * 128;
    int bc = blockIdx.x;
    int colBase = bc * 128;
    const uint32_t* Bsrc = (const uint32_t*)Bp + (size_t)bc * K * 64;

    float c[2][8][4];
#pragma unroll
    for (int i = 0; i < 2; i++)
#pragma unroll
        for (int j = 0; j < 8; j++)
#pragma unroll
            for (int q = 0; q < 4; q++) c[i][j][q] = 0.f;

    const int nc = K >> 5;

    auto stage = [&](int chunk, int slot) {
#pragma unroll
        for (int it = 0; it < 2; it++) {
            int idx = it * 256 + tid;            // 0..511
            int row = idx >> 2, cq = idx & 3;
            cp16(smem_u32(&As[slot*ASTG + row*40 + cq*8]),
                 Ah + (size_t)(rowBase + row) * K + chunk*32 + cq*8);
            cp16(smem_u32(&Bs[slot*BSTG + idx*4]),
                 Bsrc + (size_t)chunk * BSTG + idx*4);
        }
    };

    stage(0, 0); cp_commit();
    stage(1, 1); cp_commit();

    for (int i = 0; i < nc; i++) {
        if (i + 2 < nc) stage(i + 2, (i + 2) & 3);
        cp_commit();
        cp_wait<2>();
        __syncthreads();

        int slot = i & 3;
        const uint32_t* Au = (const uint32_t*)&As[slot*ASTG];
        const uint32_t* Bu = &Bs[slot*BSTG];
#pragma unroll
        for (int kk = 0; kk < 2; kk++) {
            uint32_t af[2][4];
#pragma unroll
            for (int mt = 0; mt < 2; mt++) {
                int rb = (wm*32 + mt*16 + gid)*20 + kk*8 + tg;
                af[mt][0] = Au[rb];
                af[mt][1] = Au[rb + 160];      // +8 rows
                af[mt][2] = Au[rb + 4];        // +8 k halves
                af[mt][3] = Au[rb + 164];
            }
#pragma unroll
            for (int p = 0; p < 4; p++) {
                uint4 bv = *(const uint4*)&Bu[kk*1024 + ((wn*4 + p)*32 + lane)*4];
                mma_f16(c[0][2*p],   af[0], bv.x, bv.y);
                mma_f16(c[0][2*p+1], af[0], bv.z, bv.w);
                mma_f16(c[1][2*p],   af[1], bv.x, bv.y);
                mma_f16(c[1][2*p+1], af[1], bv.z, bv.w);
            }
        }
    }

    // ---- epilogue: direct stores (+bias) ----
#pragma unroll
    for (int mt = 0; mt < 2; mt++) {
        int r0 = rowBase + wm*32 + mt*16 + gid;
#pragma unroll
        for (int nb = 0; nb < 8; nb++) {
            int col = colBase + wn*64 + nb*8 + tg*2;
            if (col < N) {
                float b0 = bias[col], b1 = bias[col + 1];
                *(float2*)&C[(size_t)r0 * N + col] =
                    make_float2(c[mt][nb][0] + b0, c[mt][nb][1] + b1);
                *(float2*)&C[(size_t)(r0 + 8) * N + col] =
                    make_float2(c[mt][nb][2] + b0, c[mt][nb][3] + b1);
            }
        }
    }
}

// ---------------- software grid barrier ----------------
__device__ __forceinline__ void grid_barrier(int dir) {
    __syncthreads();
    if (threadIdx.x == 0) {
        __threadfence();
        volatile unsigned* gen = &g_gen[dir];
        unsigned old = *gen;
        unsigned a = atomicAdd(&g_cnt[dir], 1u);
        if (a == 63u) {
            g_cnt[dir] = 0u;
            __threadfence();
            *gen = old + 1u;
        } else {
            while (*gen == old) { }
        }
        __threadfence();
    }
    __syncthreads();
}

// ---------------- persistent bidirectional LSTM layer (fp32, fp16 y out) ----------------
__global__ __launch_bounds__(128)
void lstm_layer_k(const float* __restrict__ xwf, const float* __restrict__ xwb,
                  const int* __restrict__ tok, __half* __restrict__ y)
{
    extern __shared__ float smf[];
    float* sw  = smf;
    float* shh = smf + 512*32;

    int dir = blockIdx.x >> 6;
    int ub  = blockIdx.x & 63;
    int u0  = ub * 8;
    int tid = threadIdx.x;
    int uloc = tid & 7;
    int bp   = tid >> 3;
    int b0 = bp * 2, b1 = b0 + 1;
    int u = u0 + uloc;

    const float* xw = dir ? xwb : xwf;
    const float* wr = g_wr[dir];

    for (int i = tid; i < 512*8; i += 128) {
        int k  = i >> 3;
        int c4 = i & 7;
        ((float4*)sw)[i] = *(const float4*)&wr[(size_t)k * G4 + u0*4 + c4*4];
    }
    for (int i = tid; i < 8*32; i += 128) {
        int bb = i >> 3;
        g_hs[dir][0][bb * U_ + u0 + (i & 7)] = 0.f;
    }
    float c0 = 0.f, c1 = 0.f, hp0 = 0.f, hp1 = 0.f;
    __threadfence();
    grid_barrier(dir);

    for (int s = 0; s < T_; s++) {
        int t = dir ? (T_ - 1 - s) : s;
        const float* hread  = g_hs[dir][s & 1];
        float*       hwrite = g_hs[dir][(s & 1) ^ 1];

        // Prefetch gate pre-activations + masks early (independent of h staging).
        size_t base0 = ((size_t)b0 * T_ + t) * G4;
        size_t base1 = ((size_t)b1 * T_ + t) * G4;
        float xi0 = xw[base0 + 0*U_ + u], xf0 = xw[base0 + 1*U_ + u];
        float xg0 = xw[base0 + 2*U_ + u], xo0 = xw[base0 + 3*U_ + u];
        float xi1 = xw[base1 + 0*U_ + u], xf1 = xw[base1 + 1*U_ + u];
        float xg1 = xw[base1 + 2*U_ + u], xo1 = xw[base1 + 3*U_ + u];
        int m0 = tok[b0 * T_ + t];
        int m1 = tok[b1 * T_ + t];

        for (int i = tid; i < 32*128; i += 128) {
            int bb = i >> 7;
            int kq = i & 127;
            *(float4*)&shh[bb * HSTRIDE + kq*4] =
                *(const float4*)&hread[bb * U_ + kq*4];
        }
        __syncthreads();

        float acc0[4] = {0.f,0.f,0.f,0.f};
        float acc1[4] = {0.f,0.f,0.f,0.f};
        const float* hr0 = &shh[b0 * HSTRIDE];
        const float* hr1 = &shh[b1 * HSTRIDE];

#pragma unroll 4
        for (int k = 0; k < U_; k += 4) {
            float4 hv0 = *(const float4*)&hr0[k];
            float4 hv1 = *(const float4*)&hr1[k];
            float h0a[4] = {hv0.x, hv0.y, hv0.z, hv0.w};
            float h1a[4] = {hv1.x, hv1.y, hv1.z, hv1.w};
#pragma unroll
            for (int j = 0; j < 4; j++) {
                float4 w = *(const float4*)&sw[(k + j)*32 + uloc*4];
                acc0[0] = fmaf(h0a[j], w.x, acc0[0]);
                acc0[1] = fmaf(h0a[j], w.y, acc0[1]);
                acc0[2] = fmaf(h0a[j], w.z, acc0[2]);
                acc0[3] = fmaf(h0a[j], w.w, acc0[3]);
                acc1[0] = fmaf(h1a[j], w.x, acc1[0]);
                acc1[1] = fmaf(h1a[j], w.y, acc1[1]);
                acc1[2] = fmaf(h1a[j], w.z, acc1[2]);
                acc1[3] = fmaf(h1a[j], w.w, acc1[3]);
            }
        }

        {
            float zi = acc0[0] + xi0;
            float zf = acc0[1] + xf0;
            float zg = acc0[2] + xg0;
            float zo = acc0[3] + xo0;
            float ig = 1.f / (1.f + expf(-zi));
            float fg = 1.f / (1.f + expf(-zf));
            float gg = tanhf(zg);
            float og = 1.f / (1.f + expf(-zo));
            float cn = fg * c0 + ig * gg;
            float hn = og * tanhf(cn);
            if (m0 != 0) { c0 = cn; hp0 = hn; }
            hwrite[b0 * U_ + u] = hp0;
            y[((size_t)b0 * T_ + t) * (2*U_) + dir * U_ + u] = __float2half_rn(hp0);
        }
        {
            float zi = acc1[0] + xi1;
            float zf = acc1[1] + xf1;
            float zg = acc1[2] + xg1;
            float zo = acc1[3] + xo1;
            float ig = 1.f / (1.f + expf(-zi));
            float fg = 1.f / (1.f + expf(-zf));
            float gg = tanhf(zg);
            float og = 1.f / (1.f + expf(-zo));
            float cn = fg * c1 + ig * gg;
            float hn = og * tanhf(cn);
            if (m1 != 0) { c1 = cn; hp1 = hn; }
            hwrite[b1 * U_ + u] = hp1;
            y[((size_t)b1 * T_ + t) * (2*U_) + dir * U_ + u] = __float2half_rn(hp1);
        }

        __threadfence();
        grid_barrier(dir);
    }
}

// ---------------- host ----------------
extern "C" void kernel_launch(void* const* d_in, const int* in_sizes, int n_in,
                              void* d_out, int out_size)
{
    const int*   tokens = (const int*)  d_in[0];
    const float* emb    = (const float*)d_in[1];
    const float* k1f    = (const float*)d_in[2];
    const float* r1f    = (const float*)d_in[3];
    const float* b1f    = (const float*)d_in[4];
    const float* k1b    = (const float*)d_in[5];
    const float* r1b    = (const float*)d_in[6];
    const float* b1b    = (const float*)d_in[7];
    const float* k2f    = (const float*)d_in[8];
    const float* r2f    = (const float*)d_in[9];
    const float* b2f    = (const float*)d_in[10];
    const float* k2b    = (const float*)d_in[11];
    const float* r2b    = (const float*)d_in[12];
    const float* b2b    = (const float*)d_in[13];
    const float* wd     = (const float*)d_in[14];
    const float* bd     = (const float*)d_in[15];
    float* out = (float*)d_out;

    static __half *pxh = nullptr, *ph1h, *ph2h;
    static float *pxw0, *pxw1;
    static __half2 *pwdP, *pkP0, *pkP1;
    if (!pxh) {
        cudaGetSymbolAddress((void**)&pxh,  g_xh);
        cudaGetSymbolAddress((void**)&pxw0, g_xw0);
        cudaGetSymbolAddress((void**)&pxw1, g_xw1);
        cudaGetSymbolAddress((void**)&ph1h, g_h1h);
        cudaGetSymbolAddress((void**)&ph2h, g_h2h);
        cudaGetSymbolAddress((void**)&pwdP, g_wdP);
        cudaGetSymbolAddress((void**)&pkP0, g_kP);
        pkP1 = pkP0 + (size_t)G4 * 2 * U_ / 2;
        cudaFuncSetAttribute(lstm_layer_k,
                             cudaFuncAttributeMaxDynamicSharedMemorySize,
                             (512*32 + 32*HSTRIDE) * sizeof(float));
        cudaFuncSetAttribute(f16_gemm_k,
                             cudaFuncAttributeMaxDynamicSharedMemorySize,
                             4*ASTG*2 + 4*BSTG*4);
    }
    const int lstm_smem = (512*32 + 32*HSTRIDE) * sizeof(float);
    const int gemm_smem = 4*ASTG*2 + 4*BSTG*4;

    embed_k<<<(BT*E_/8)/256, 256>>>(tokens, emb);

    // ---- layer 1 (K=256, N=2048) ----
    reorder_k<<<(U_*G4)/256, 256>>>(r1f, r1b);
    pack_b_k<<<(G4*E_/2)/256, 256>>>(k1f, pkP0, E_, G4);
    pack_b_k<<<(G4*E_/2)/256, 256>>>(k1b, pkP1, E_, G4);
    f16_gemm_k<<<dim3(G4/128, BT/128), 256, gemm_smem>>>(pxh, pkP0, b1f, pxw0, G4, E_);
    f16_gemm_k<<<dim3(G4/128, BT/128), 256, gemm_smem>>>(pxh, pkP1, b1b, pxw1, G4, E_);
    lstm_layer_k<<<128, 128, lstm_smem>>>(pxw0, pxw1, tokens, ph1h);

    // ---- layer 2 (K=1024, N=2048) ----
    reorder_k<<<(U_*G4)/256, 256>>>(r2f, r2b);
    pack_b_k<<<(G4*2*U_/2)/256, 256>>>(k2f, pkP0, 2*U_, G4);
    pack_b_k<<<(G4*2*U_/2)/256, 256>>>(k2b, pkP1, 2*U_, G4);
    f16_gemm_k<<<dim3(G4/128, BT/128), 256, gemm_smem>>>(ph1h, pkP0, b2f, pxw0, G4, 2*U_);
    f16_gemm_k<<<dim3(G4/128, BT/128), 256, gemm_smem>>>(ph1h, pkP1, b2b, pxw1, G4, 2*U_);
    lstm_layer_k<<<128, 128, lstm_smem>>>(pxw0, pxw1, tokens, ph2h);

    // ---- output projection (K=1024, N=8000 padded 8064) ----
    pack_b_k<<<((size_t)VPAD*2*U_/2)/256, 256>>>(wd, pwdP, 2*U_, V_);
    f16_gemm_k<<<dim3(VPAD/128, BT/128), 256, gemm_smem>>>(ph2h, pwdP, bd, out, V_, 2*U_);
}

// round 11
// speedup vs baseline: 2.6254x; 1.3346x over previous
#include <cuda_runtime.h>
#include <cuda_fp16.h>
#include <math.h>
#include <stdint.h>

#define B_ 32
#define T_ 512
#define V_ 8000
#define E_ 256
#define U_ 512
#define G4 (4*U_)     // 2048
#define BT (B_*T_)    // 16384
#define VPAD 8064

#define ASTG 5120     // halves per A stage: 128 rows * 40
#define BSTG 2048     // b32 per B stage
#define HROW 520      // h staging row stride (halves)

// ---------------- static device scratch ----------------
__device__ __half g_xh [BT*E_];
__device__ float  g_xw0[(size_t)BT*G4];
__device__ float  g_xw1[(size_t)BT*G4];
__device__ __half g_h1h[(size_t)BT*2*U_];
__device__ __half g_h2h[(size_t)BT*2*U_];
__device__ float  g_wr [2][U_*G4];
__device__ __half g_hsh[2][2][B_*U_];            // fp16 h state [dir][parity]
__device__ __half2 g_wdP[(size_t)VPAD*2*U_/2];
__device__ __half2 g_kP [2][(size_t)G4*2*U_/2];
__device__ unsigned g_gen[2];
__device__ unsigned g_cnt[2];

// ---------------- helpers ----------------
__device__ __forceinline__ uint32_t smem_u32(const void* p) {
    uint32_t a;
    asm("{ .reg .u64 t; cvta.to.shared.u64 t, %1; cvt.u32.u64 %0, t; }" : "=r"(a) : "l"(p));
    return a;
}
__device__ __forceinline__ void cp16(uint32_t dst, const void* src) {
    asm volatile("cp.async.ca.shared.global [%0], [%1], 16;" :: "r"(dst), "l"(src));
}
__device__ __forceinline__ void cp_commit() {
    asm volatile("cp.async.commit_group;" ::: "memory");
}
template <int N>
__device__ __forceinline__ void cp_wait() {
    asm volatile("cp.async.wait_group %0;" :: "n"(N) : "memory");
}
__device__ __forceinline__ void mma_f16(float c[4], const uint32_t a[4], uint32_t b0, uint32_t b1) {
    asm volatile(
        "mma.sync.aligned.m16n8k16.row.col.f32.f16.f16.f32 "
        "{%0,%1,%2,%3}, {%4,%5,%6,%7}, {%8,%9}, {%0,%1,%2,%3};"
        : "+f"(c[0]), "+f"(c[1]), "+f"(c[2]), "+f"(c[3])
        : "r"(a[0]), "r"(a[1]), "r"(a[2]), "r"(a[3]), "r"(b0), "r"(b1));
}
__device__ __forceinline__ void ldmat_x4(uint32_t r[4], uint32_t addr) {
    asm volatile("ldmatrix.sync.aligned.m8n8.x4.shared.b16 {%0,%1,%2,%3}, [%4];"
                 : "=r"(r[0]), "=r"(r[1]), "=r"(r[2]), "=r"(r[3]) : "r"(addr));
}

// ---------------- embedding gather -> fp16 ----------------
__global__ void embed_k(const int* __restrict__ tok, const float* __restrict__ emb) {
    int i = blockIdx.x * 256 + threadIdx.x;
    int row = i >> 5;
    int c8  = i & 31;
    int t = tok[row];
    const float4* s = (const float4*)(emb + (size_t)t * E_ + c8 * 8);
    float4 v0 = s[0], v1 = s[1];
    __half2 h[4];
    h[0] = __floats2half2_rn(v0.x, v0.y);
    h[1] = __floats2half2_rn(v0.z, v0.w);
    h[2] = __floats2half2_rn(v1.x, v1.y);
    h[3] = __floats2half2_rn(v1.z, v1.w);
    *(uint4*)&g_xh[(size_t)row * E_ + c8 * 8] = *(uint4*)h;
}

// ---------------- Wr reorder: [k][g*U+u] -> [k][u*4+g] ----------------
__global__ void reorder_k(const float* __restrict__ rf, const float* __restrict__ rb) {
    int i = blockIdx.x * 256 + threadIdx.x;
    int k = i / G4;
    int c = i % G4;
    int u = c >> 2, g = c & 3;
    g_wr[0][i] = rf[(size_t)k * G4 + g * U_ + u];
    g_wr[1][i] = rb[(size_t)k * G4 + g * U_ + u];
}

// ---------------- pack B[K][N] -> fp16 fragment order (for GEMM) ----------------
__global__ void pack_b_k(const float* __restrict__ in, __half2* __restrict__ out,
                         int K, int N) {
    size_t o = (size_t)blockIdx.x * 256 + threadIdx.x;
    int per_bc = K * 64;
    int bc  = (int)(o / per_bc);
    int rem = (int)(o % per_bc);
    int kt = rem >> 10;
    int r2 = rem & 1023;
    int pg = r2 >> 7;
    int lr = r2 & 127;
    int lane = lr >> 2, r = lr & 3;
    int nt = 2*pg + (r >> 1);
    int breg = r & 1;
    int g = lane >> 2, t4 = lane & 3;
    int k = kt*16 + breg*8 + 2*t4;
    int n = bc*128 + nt*8 + g;
    float v0 = (n < N) ? in[(size_t)k * N + n] : 0.f;
    float v1 = (n < N) ? in[(size_t)(k+1) * N + n] : 0.f;
    out[o] = __floats2half2_rn(v0, v1);
}

// ---------------- fp16 mma GEMM (unchanged from R10) ----------------
__global__ __launch_bounds__(256)
void f16_gemm_k(const __half* __restrict__ Ah, const __half2* __restrict__ Bp,
                const float* __restrict__ bias, float* __restrict__ C,
                int N, int K)
{
    extern __shared__ __half sm[];
    __half* As = sm;
    uint32_t* Bs = (uint32_t*)(sm + 4*ASTG);

    int tid = threadIdx.x;
    int wid = tid >> 5, lane = tid & 31;
    int wm = wid >> 1, wn = wid & 1;
    int gid = lane >> 2, tg = lane & 3;
    int rowBase = blockIdx.y * 128;
    int bc = blockIdx.x;
    int colBase = bc * 128;
    const uint32_t* Bsrc = (const uint32_t*)Bp + (size_t)bc * K * 64;

    float c[2][8][4];
#pragma unroll
    for (int i = 0; i < 2; i++)
#pragma unroll
        for (int j = 0; j < 8; j++)
#pragma unroll
            for (int q = 0; q < 4; q++) c[i][j][q] = 0.f;

    const int nc = K >> 5;

    auto stage = [&](int chunk, int slot) {
#pragma unroll
        for (int it = 0; it < 2; it++) {
            int idx = it * 256 + tid;
            int row = idx >> 2, cq = idx & 3;
            cp16(smem_u32(&As[slot*ASTG + row*40 + cq*8]),
                 Ah + (size_t)(rowBase + row) * K + chunk*32 + cq*8);
            cp16(smem_u32(&Bs[slot*BSTG + idx*4]),
                 Bsrc + (size_t)chunk * BSTG + idx*4);
        }
    };

    stage(0, 0); cp_commit();
    stage(1, 1); cp_commit();

    for (int i = 0; i < nc; i++) {
        if (i + 2 < nc) stage(i + 2, (i + 2) & 3);
        cp_commit();
        cp_wait<2>();
        __syncthreads();

        int slot = i & 3;
        const uint32_t* Au = (const uint32_t*)&As[slot*ASTG];
        const uint32_t* Bu = &Bs[slot*BSTG];
#pragma unroll
        for (int kk = 0; kk < 2; kk++) {
            uint32_t af[2][4];
#pragma unroll
            for (int mt = 0; mt < 2; mt++) {
                int rb = (wm*32 + mt*16 + gid)*20 + kk*8 + tg;
                af[mt][0] = Au[rb];
                af[mt][1] = Au[rb + 160];
                af[mt][2] = Au[rb + 4];
                af[mt][3] = Au[rb + 164];
            }
#pragma unroll
            for (int p = 0; p < 4; p++) {
                uint4 bv = *(const uint4*)&Bu[kk*1024 + ((wn*4 + p)*32 + lane)*4];
                mma_f16(c[0][2*p],   af[0], bv.x, bv.y);
                mma_f16(c[0][2*p+1], af[0], bv.z, bv.w);
                mma_f16(c[1][2*p],   af[1], bv.x, bv.y);
                mma_f16(c[1][2*p+1], af[1], bv.z, bv.w);
            }
        }
    }

#pragma unroll
    for (int mt = 0; mt < 2; mt++) {
        int r0 = rowBase + wm*32 + mt*16 + gid;
#pragma unroll
        for (int nb = 0; nb < 8; nb++) {
            int col = colBase + wn*64 + nb*8 + tg*2;
            if (col < N) {
                float b0 = bias[col], b1 = bias[col + 1];
                *(float2*)&C[(size_t)r0 * N + col] =
                    make_float2(c[mt][nb][0] + b0, c[mt][nb][1] + b1);
                *(float2*)&C[(size_t)(r0 + 8) * N + col] =
                    make_float2(c[mt][nb][2] + b0, c[mt][nb][3] + b1);
            }
        }
    }
}

// ---------------- software grid barrier ----------------
__device__ __forceinline__ void grid_barrier(int dir) {
    __syncthreads();
    if (threadIdx.x == 0) {
        __threadfence();
        volatile unsigned* gen = &g_gen[dir];
        unsigned old = *gen;
        unsigned a = atomicAdd(&g_cnt[dir], 1u);
        if (a == 63u) {
            g_cnt[dir] = 0u;
            __threadfence();
            *gen = old + 1u;
        } else {
            while (*gen == old) { }
        }
        __threadfence();
    }
    __syncthreads();
}

// ---------------- persistent bidirectional LSTM layer — mma recurrence ----------------
// 128 CTAs: dir = bid>>6, ub = bid&63 (8 units). 128 threads = 4 warps.
// Per step: C[32b, 32cols] = h[32,512](fp16) @ WrSlice(fp16 frags), fp32 acc.
// Warp w owns cols [8w, 8w+8) = units {2w, 2w+1} x 4 gates.
__global__ __launch_bounds__(128)
void lstm_layer_k(const float* __restrict__ xwf, const float* __restrict__ xwb,
                  const int* __restrict__ tok, __half* __restrict__ y)
{
    extern __shared__ __half smh[];
    uint32_t* swB = (uint32_t*)smh;              // 8192 uint32 = 32 KB B-frags
    __half*   shh = smh + 16384;                 // 32 x HROW halves staged h

    int dir = blockIdx.x >> 6;
    int ub  = blockIdx.x & 63;
    int u0  = ub * 8;
    int tid = threadIdx.x;
    int w   = tid >> 5, lane = tid & 31;
    int gid = lane >> 2, tg = lane & 3;

    const float* xw = dir ? xwb : xwf;
    const float* wr = g_wr[dir];

    // ---- pack Wr slice into B-fragment order (once) ----
    for (int i = tid; i < 8192; i += 128) {
        int r  = i & 1;
        int ln = (i >> 1) & 31;
        int w_ = (i >> 6) & 3;
        int kt = i >> 8;
        int n = w_*8 + (ln >> 2);
        int k = kt*16 + r*8 + 2*(ln & 3);
        __half2 hv = __floats2half2_rn(wr[(size_t)k * G4 + u0*4 + n],
                                       wr[(size_t)(k+1) * G4 + u0*4 + n]);
        swB[i] = *(uint32_t*)&hv;
    }
    // zero initial h (parity 0) for our units
    for (int i = tid; i < 8*32; i += 128) {
        int bb = i >> 3;
        g_hsh[dir][0][bb * U_ + u0 + (i & 7)] = __float2half_rn(0.f);
    }

    // cell ownership (even-tg lanes): unit uu, 4 batches (j: b = (j>>1)*16 + gid + (j&1)*8)
    int tg2 = tg >> 1;
    int uu  = u0 + w*2 + tg2;
    float cst[4] = {0.f,0.f,0.f,0.f};
    float hst[4] = {0.f,0.f,0.f,0.f};

    __threadfence();
    grid_barrier(dir);

    for (int s = 0; s < T_; s++) {
        int t = dir ? (T_ - 1 - s) : s;
        const __half* hread  = g_hsh[dir][s & 1];
        __half*       hwrite = g_hsh[dir][(s & 1) ^ 1];

        // ---- prefetch xw gates + masks (independent of h) ----
        float xwv[2][4];      // [col offset c][batch j]
        int   msk[4];
#pragma unroll
        for (int j = 0; j < 4; j++) {
            int b = (j >> 1)*16 + gid + (j & 1)*8;
            msk[j] = tok[b * T_ + t];
#pragma unroll
            for (int c = 0; c < 2; c++) {
                int col = w*8 + 2*tg + c;
                int gg = col & 3;
                int uc = u0 + (col >> 2);
                xwv[c][j] = xw[((size_t)b * T_ + t) * G4 + gg * U_ + uc];
            }
        }

        // ---- stage h fp16 into SMEM ----
        for (int i = tid; i < 2048; i += 128) {
            int row = i >> 6, ch = i & 63;
            cp16(smem_u32(&shh[row * HROW + ch * 8]),
                 hread + row * U_ + ch * 8);
        }
        cp_commit();
        cp_wait<0>();
        __syncthreads();

        // ---- mma mainloop: 32 k-steps ----
        float acc[2][4];
#pragma unroll
        for (int mt = 0; mt < 2; mt++)
#pragma unroll
            for (int q = 0; q < 4; q++) acc[mt][q] = 0.f;

        int r8 = lane & 7;
        int quad = lane >> 3;
        uint32_t abase0 = smem_u32(&shh[((quad & 1)*8 + r8) * HROW + (quad >> 1)*8]);
        uint32_t abase1 = abase0 + 16 * HROW * 2;   // +16 rows (bytes)

        const uint32_t* bptr = &swB[(0*4 + w)*64 + lane*2];
#pragma unroll 4
        for (int kt = 0; kt < 32; kt++) {
            uint32_t a0[4], a1[4];
            ldmat_x4(a0, abase0 + kt*32);           // +16 halves per kt = 32 B
            ldmat_x4(a1, abase1 + kt*32);
            uint2 bv = *(const uint2*)&swB[(kt*4 + w)*64 + lane*2];
            mma_f16(acc[0], a0, bv.x, bv.y);
            mma_f16(acc[1], a1, bv.x, bv.y);
        }
        (void)bptr;

        // ---- add xw: z[mt][q], batch = mt*16 + gid + (q>=2)*8, col offset q&1 ----
        float z[2][4];
#pragma unroll
        for (int mt = 0; mt < 2; mt++)
#pragma unroll
            for (int q = 0; q < 4; q++) {
                int j = mt*2 + (q >> 1);
                z[mt][q] = acc[mt][q] + xwv[q & 1][j];
            }

        // ---- exchange with partner lane (tg^1): even gets (g,o), odd gives ----
        float rz[2][4];
#pragma unroll
        for (int mt = 0; mt < 2; mt++)
#pragma unroll
            for (int q = 0; q < 4; q++)
                rz[mt][q] = __shfl_xor_sync(0xffffffffu, z[mt][q], 1);

        if ((tg & 1) == 0) {
#pragma unroll
            for (int j = 0; j < 4; j++) {
                int mt = j >> 1, qr = (j & 1)*2;
                float zi = z [mt][qr], zf = z [mt][qr+1];
                float zg = rz[mt][qr], zo = rz[mt][qr+1];
                float ig = 1.f / (1.f + expf(-zi));
                float fg = 1.f / (1.f + expf(-zf));
                float gg = tanhf(zg);
                float og = 1.f / (1.f + expf(-zo));
                float cn = fg * cst[j] + ig * gg;
                float hn = og * tanhf(cn);
                if (msk[j] != 0) { cst[j] = cn; hst[j] = hn; }
                int b = (j >> 1)*16 + gid + (j & 1)*8;
                __half hh = __float2half_rn(hst[j]);
                hwrite[b * U_ + uu] = hh;
                y[((size_t)b * T_ + t) * (2*U_) + dir * U_ + uu] = hh;
            }
        }

        __threadfence();
        grid_barrier(dir);
    }
}

// ---------------- host ----------------
extern "C" void kernel_launch(void* const* d_in, const int* in_sizes, int n_in,
                              void* d_out, int out_size)
{
    const int*   tokens = (const int*)  d_in[0];
    const float* emb    = (const float*)d_in[1];
    const float* k1f    = (const float*)d_in[2];
    const float* r1f    = (const float*)d_in[3];
    const float* b1f    = (const float*)d_in[4];
    const float* k1b    = (const float*)d_in[5];
    const float* r1b    = (const float*)d_in[6];
    const float* b1b    = (const float*)d_in[7];
    const float* k2f    = (const float*)d_in[8];
    const float* r2f    = (const float*)d_in[9];
    const float* b2f    = (const float*)d_in[10];
    const float* k2b    = (const float*)d_in[11];
    const float* r2b    = (const float*)d_in[12];
    const float* b2b    = (const float*)d_in[13];
    const float* wd     = (const float*)d_in[14];
    const float* bd     = (const float*)d_in[15];
    float* out = (float*)d_out;

    static __half *pxh = nullptr, *ph1h, *ph2h;
    static float *pxw0, *pxw1;
    static __half2 *pwdP, *pkP0, *pkP1;
    if (!pxh) {
        cudaGetSymbolAddress((void**)&pxh,  g_xh);
        cudaGetSymbolAddress((void**)&pxw0, g_xw0);
        cudaGetSymbolAddress((void**)&pxw1, g_xw1);
        cudaGetSymbolAddress((void**)&ph1h, g_h1h);
        cudaGetSymbolAddress((void**)&ph2h, g_h2h);
        cudaGetSymbolAddress((void**)&pwdP, g_wdP);
        cudaGetSymbolAddress((void**)&pkP0, g_kP);
        pkP1 = pkP0 + (size_t)G4 * 2 * U_ / 2;
        cudaFuncSetAttribute(lstm_layer_k,
                             cudaFuncAttributeMaxDynamicSharedMemorySize,
                             32768 + 32*HROW*2);
        cudaFuncSetAttribute(f16_gemm_k,
                             cudaFuncAttributeMaxDynamicSharedMemorySize,
                             4*ASTG*2 + 4*BSTG*4);
    }
    const int lstm_smem = 32768 + 32*HROW*2;
    const int gemm_smem = 4*ASTG*2 + 4*BSTG*4;

    embed_k<<<(BT*E_/8)/256, 256>>>(tokens, emb);

    // ---- layer 1 (K=256, N=2048) ----
    reorder_k<<<(U_*G4)/256, 256>>>(r1f, r1b);
    pack_b_k<<<(G4*E_/2)/256, 256>>>(k1f, pkP0, E_, G4);
    pack_b_k<<<(G4*E_/2)/256, 256>>>(k1b, pkP1, E_, G4);
    f16_gemm_k<<<dim3(G4/128, BT/128), 256, gemm_smem>>>(pxh, pkP0, b1f, pxw0, G4, E_);
    f16_gemm_k<<<dim3(G4/128, BT/128), 256, gemm_smem>>>(pxh, pkP1, b1b, pxw1, G4, E_);
    lstm_layer_k<<<128, 128, lstm_smem>>>(pxw0, pxw1, tokens, ph1h);

    // ---- layer 2 (K=1024, N=2048) ----
    reorder_k<<<(U_*G4)/256, 256>>>(r2f, r2b);
    pack_b_k<<<(G4*2*U_/2)/256, 256>>>(k2f, pkP0, 2*U_, G4);
    pack_b_k<<<(G4*2*U_/2)/256, 256>>>(k2b, pkP1, 2*U_, G4);
    f16_gemm_k<<<dim3(G4/128, BT/128), 256, gemm_smem>>>(ph1h, pkP0, b2f, pxw0, G4, 2*U_);
    f16_gemm_k<<<dim3(G4/128, BT/128), 256, gemm_smem>>>(ph1h, pkP1, b2b, pxw1, G4, 2*U_);
    lstm_layer_k<<<128, 128, lstm_smem>>>(pxw0, pxw1, tokens, ph2h);

    // ---- output projection (K=1024, N=8000 padded 8064) ----
    pack_b_k<<<((size_t)VPAD*2*U_/2)/256, 256>>>(wd, pwdP, 2*U_, V_);
    f16_gemm_k<<<dim3(VPAD/128, BT/128), 256, gemm_smem>>>(ph2h, pwdP, bd, out, V_, 2*U_);
}